// round 2
// baseline (speedup 1.0000x reference)
#include <cuda_runtime.h>
#include <cstdint>

#define NN   6144
#define INF  512
#define H    8
#define DH   64
#define OUTF 512          // H*DH
#define NW   192          // NN/32 mask words per row

// ---------------- scratch (device globals; no runtime alloc) ----------------
__device__ float    g_h[NN * OUTF];          // h[i][head*64+d]  (12.6 MB)
__device__ float4   g_ai[H * NN];            // {u, u5, -a0, 0}
__device__ float4   g_aj[H * NN];            // {a1, v, v5, 0}
__device__ unsigned g_bits[NN * NW];         // adj bitmask, row-major (4.7 MB)

// ---------------- packed f32x2 helpers ----------------
__device__ __forceinline__ void fma2(unsigned long long& d, unsigned long long a,
                                     unsigned long long b, unsigned long long c) {
    asm("fma.rn.f32x2 %0, %1, %2, %3;" : "=l"(d) : "l"(a), "l"(b), "l"(c));
}
__device__ __forceinline__ unsigned long long pack2(float x) {
    unsigned long long r;
    asm("mov.b64 %0, {%1, %1};" : "=l"(r) : "f"(x));
    return r;
}

// =====================================================================
// Kernel A: h = x @ W^T + b    (M=6144, N=512, K=512)
// 128x64 tile, 256 threads, 8x4 micro-tile
// =====================================================================
__global__ __launch_bounds__(256) void gemm_h_kernel(
    const float* __restrict__ x, const float* __restrict__ W,
    const float* __restrict__ b) {
    __shared__ float xs[128][36];   // [m][k]
    __shared__ float ws[32][68];    // [k][n]
    const int tid = threadIdx.x;
    const int tm = tid >> 4;        // 0..15 -> 8 rows each
    const int tn = tid & 15;        // 0..15 -> 4 cols each
    const int m0 = blockIdx.x * 128;
    const int n0 = blockIdx.y * 64;

    float acc[8][4];
#pragma unroll
    for (int r = 0; r < 8; r++)
#pragma unroll
        for (int c = 0; c < 4; c++) acc[r][c] = 0.f;

    for (int kb = 0; kb < INF; kb += 32) {
        // load x tile 128x32 (4 float4 per thread)
#pragma unroll
        for (int p = 0; p < 4; p++) {
            int idx = tid + p * 256;
            int m = idx >> 3, k4 = idx & 7;
            float4 v = *(const float4*)&x[(m0 + m) * INF + kb + k4 * 4];
            *(float4*)&xs[m][k4 * 4] = v;
        }
        // load W tile 64x32, store transposed (2 float4 per thread)
#pragma unroll
        for (int p = 0; p < 2; p++) {
            int idx = tid + p * 256;
            int n = idx >> 3, k4 = idx & 7;
            float4 v = *(const float4*)&W[(n0 + n) * INF + kb + k4 * 4];
            ws[k4 * 4 + 0][n] = v.x;
            ws[k4 * 4 + 1][n] = v.y;
            ws[k4 * 4 + 2][n] = v.z;
            ws[k4 * 4 + 3][n] = v.w;
        }
        __syncthreads();
#pragma unroll 8
        for (int k = 0; k < 32; k++) {
            float a[8];
#pragma unroll
            for (int r = 0; r < 8; r++) a[r] = xs[tm * 8 + r][k];
            float4 bv = *(const float4*)&ws[k][tn * 4];
#pragma unroll
            for (int r = 0; r < 8; r++) {
                acc[r][0] += a[r] * bv.x;
                acc[r][1] += a[r] * bv.y;
                acc[r][2] += a[r] * bv.z;
                acc[r][3] += a[r] * bv.w;
            }
        }
        __syncthreads();
    }
    float4 bias = *(const float4*)&b[n0 + tn * 4];
#pragma unroll
    for (int r = 0; r < 8; r++) {
        float4 o;
        o.x = acc[r][0] + bias.x;
        o.y = acc[r][1] + bias.y;
        o.z = acc[r][2] + bias.z;
        o.w = acc[r][3] + bias.w;
        *(float4*)&g_h[(m0 + tm * 8 + r) * OUTF + n0 + tn * 4] = o;
    }
}

// =====================================================================
// Kernel B: per-(head,node) attention params. One warp per (i, head).
// =====================================================================
__global__ __launch_bounds__(256) void param_kernel(const float* __restrict__ aw) {
    const int tid = threadIdx.x;
    const int gw = blockIdx.x * 8 + (tid >> 5);
    const int lane = tid & 31;
    const int i = gw >> 3;
    const int hd = gw & 7;
    if (i >= NN) return;

    float h0 = g_h[i * OUTF + hd * 64 + lane];
    float h1 = g_h[i * OUTF + hd * 64 + lane + 32];
    float w00 = aw[hd * 128 + lane * 2 + 0];
    float w01 = aw[hd * 128 + lane * 2 + 1];
    float w10 = aw[hd * 128 + (lane + 32) * 2 + 0];
    float w11 = aw[hd * 128 + (lane + 32) * 2 + 1];
    float a0 = h0 * w00 + h1 * w10;
    float a1 = h0 * w01 + h1 * w11;
#pragma unroll
    for (int o = 16; o > 0; o >>= 1) {
        a0 += __shfl_xor_sync(0xffffffffu, a0, o);
        a1 += __shfl_xor_sync(0xffffffffu, a1, o);
    }
    if (lane == 0) {
        float4 ai, aj;
        ai.x = expf(a0);
        ai.y = expf(0.2f * a0);
        ai.z = -a0;
        ai.w = 0.f;
        aj.x = a1;
        aj.y = expf(a1);
        aj.z = expf(0.2f * a1);
        aj.w = 0.f;
        g_ai[hd * NN + i] = ai;
        g_aj[hd * NN + i] = aj;
    }
}

// =====================================================================
// Kernel C: adj -> row-major bitmask. One warp per (row, 32-col word).
// =====================================================================
__global__ __launch_bounds__(256) void bits_kernel(const int* __restrict__ adj) {
    const int gw = blockIdx.x * 8 + (threadIdx.x >> 5);
    const int lane = threadIdx.x & 31;
    const int i = gw / NW;
    const int jw = gw % NW;
    if (i >= NN) return;
    int v = adj[i * NN + jw * 32 + lane];
    unsigned m = __ballot_sync(0xffffffffu, v > 0);
    if (lane == 0) g_bits[i * NW + jw] = m;
}

// =====================================================================
// Kernel D: fused masked-softmax attention + P@h.
// Grid (48 i-tiles, 8 heads). ITILE=128, JTILE=64, 256 threads.
// =====================================================================
#define EPAD 136
#define HPAD 68
#define SMEM_D ((64 * EPAD + 64 * HPAD + 512 + 256 + 256) * 4)  // 56320 B

__global__ __launch_bounds__(256, 3) void attn_kernel(float* __restrict__ out) {
    extern __shared__ float sm[];
    float* Et = sm;                          // [64][136] Et[j][i]
    float* hs = sm + 64 * EPAD;              // [64][68]
    float4* ai4 = (float4*)(hs + 64 * HPAD); // [128]
    float4* aj4 = ai4 + 128;                 // [64]
    float* lp = (float*)(aj4 + 64);          // [256]

    const int tid = threadIdx.x;
    const int hd = blockIdx.y;
    const int i0 = blockIdx.x * 128;

    // stage per-i params once
    if (tid < 128) ai4[tid] = g_ai[hd * NN + i0 + tid];

    // E-build identity (fixed across tiles)
    const int eb_i = tid & 127;
    const int eb_jw = tid >> 7;  // 0 or 1 (which 32-j half of the tile)
    float lacc = 0.f;

    // GEMM identity
    const int ti = tid >> 3;     // 0..31 -> 4 i-rows each
    const int td = tid & 7;      // 0..7  -> 8 d-cols each
    const int dbase = td * 8;

    unsigned long long acc[2][8];
#pragma unroll
    for (int p = 0; p < 2; p++)
#pragma unroll
        for (int d = 0; d < 8; d++) acc[p][d] = 0ull;

    for (int jt = 0; jt < NN / 64; jt++) {
        const int j0 = jt * 64;
        __syncthreads();  // previous GEMM done reading Et/hs (also covers ai4 staging)
        // ---- stage aj + h tile ----
        if (tid < 64) aj4[tid] = g_aj[hd * NN + j0 + tid];
#pragma unroll
        for (int p = 0; p < 4; p++) {
            int idx = tid + p * 256;
            int r = idx >> 4, c4 = idx & 15;
            float4 v = *(const float4*)&g_h[(j0 + r) * OUTF + hd * 64 + c4 * 4];
            *(float4*)&hs[r * HPAD + c4 * 4] = v;
        }
        __syncthreads();
        // ---- E build (transposed) + row-sum partials ----
        {
            float4 ai = ai4[eb_i];
            unsigned mw = g_bits[(i0 + eb_i) * NW + (j0 >> 5) + eb_jw];
            const int jb = eb_jw * 32;
#pragma unroll 8
            for (int k = 0; k < 32; k++) {
                float4 aj = aj4[jb + k];
                float e = (aj.x > ai.z) ? (ai.x * aj.y) : (ai.y * aj.z);
                e = ((mw >> k) & 1u) ? e : 0.f;
                Et[(jb + k) * EPAD + eb_i] = e;
                lacc += e;
            }
        }
        __syncthreads();
        // ---- GEMM: acc[i][d] += E[i][j] * h[j][d], packed over i-pairs ----
        const float* etb = &Et[ti * 4];
        const float* hsb = &hs[dbase];
#pragma unroll 4
        for (int j = 0; j < 64; j++) {
            ulonglong2 ev = *(const ulonglong2*)(etb + j * EPAD);  // (e0,e1),(e2,e3)
            float4 h0 = *(const float4*)(hsb + j * HPAD);
            float4 h1 = *(const float4*)(hsb + j * HPAD + 4);
            float hv[8] = {h0.x, h0.y, h0.z, h0.w, h1.x, h1.y, h1.z, h1.w};
#pragma unroll
            for (int d = 0; d < 8; d++) {
                unsigned long long hh = pack2(hv[d]);
                fma2(acc[0][d], ev.x, hh, acc[0][d]);
                fma2(acc[1][d], ev.y, hh, acc[1][d]);
            }
        }
    }
    __syncthreads();
    lp[tid] = lacc;
    __syncthreads();

    // ---- epilogue: normalize and store ----
    union F2 { unsigned long long u; float f[2]; };
#pragma unroll
    for (int ii = 0; ii < 4; ii++) {
        int il = ti * 4 + ii;
        float l = lp[il] + lp[il + 128];
        float inv = (l > 0.f) ? (1.0f / l) : 0.f;
        int pair = ii >> 1, half = ii & 1;
        float4 o0, o1;
        F2 t;
        t.u = acc[pair][0]; o0.x = t.f[half] * inv;
        t.u = acc[pair][1]; o0.y = t.f[half] * inv;
        t.u = acc[pair][2]; o0.z = t.f[half] * inv;
        t.u = acc[pair][3]; o0.w = t.f[half] * inv;
        t.u = acc[pair][4]; o1.x = t.f[half] * inv;
        t.u = acc[pair][5]; o1.y = t.f[half] * inv;
        t.u = acc[pair][6]; o1.z = t.f[half] * inv;
        t.u = acc[pair][7]; o1.w = t.f[half] * inv;
        float* dst = &out[(i0 + il) * OUTF + hd * 64 + dbase];
        *(float4*)dst = o0;
        *(float4*)(dst + 4) = o1;
    }
}

// =====================================================================
extern "C" void kernel_launch(void* const* d_in, const int* in_sizes, int n_in,
                              void* d_out, int out_size) {
    const float* x = (const float*)d_in[0];
    const int* adj = (const int*)d_in[1];
    const float* W = (const float*)d_in[2];
    const float* b = (const float*)d_in[3];
    const float* aw = (const float*)d_in[4];
    float* out = (float*)d_out;

    cudaFuncSetAttribute(attn_kernel, cudaFuncAttributeMaxDynamicSharedMemorySize,
                         SMEM_D);

    gemm_h_kernel<<<dim3(NN / 128, OUTF / 64), 256>>>(x, W, b);
    param_kernel<<<(NN * H) / 8, 256>>>(aw);
    bits_kernel<<<(NN * NW) / 8, 256>>>(adj);
    attn_kernel<<<dim3(NN / 128, H), 256, SMEM_D>>>(out);
}

// round 5
// speedup vs baseline: 2.9204x; 2.9204x over previous
#include <cuda_runtime.h>
#include <cuda_bf16.h>
#include <cstdint>

#define NN   6144
#define INF  512
#define H    8
#define OUTF 512
#define NW   192

// ---------------- scratch ----------------
__device__ __align__(16) float    g_h[NN * OUTF];
__device__ __align__(16) float4   g_ai[H * NN];            // {u, u5, -a0, 0}
__device__ __align__(16) float4   g_aj[H * NN];            // {a1, v, v5, 0}
__device__ __align__(16) unsigned g_bits[NN * NW];
__device__ __align__(16) __nv_bfloat16 g_hb_hi[H * NN * 64];   // [head][j][d]
__device__ __align__(16) __nv_bfloat16 g_hb_lo[H * NN * 64];

// ---------------- helpers ----------------
__device__ __forceinline__ unsigned pack_bf16x2(float hi, float lo) {
    unsigned r;
    asm("cvt.rn.bf16x2.f32 %0, %1, %2;" : "=r"(r) : "f"(hi), "f"(lo));
    return r;
}
__device__ __forceinline__ uint32_t smem_u32(const void* p) {
    uint32_t a;
    asm("{ .reg .u64 t; cvta.to.shared.u64 t, %1; cvt.u32.u64 %0, t; }" : "=r"(a) : "l"(p));
    return a;
}
__device__ __forceinline__ void cp16(uint32_t dst, const void* src) {
    asm volatile("cp.async.cg.shared.global [%0], [%1], 16;" :: "r"(dst), "l"(src));
}
__device__ __forceinline__ void ldm4t(uint32_t addr, unsigned& r0, unsigned& r1,
                                      unsigned& r2, unsigned& r3) {
    asm volatile("ldmatrix.sync.aligned.m8n8.x4.trans.shared.b16 {%0,%1,%2,%3}, [%4];"
                 : "=r"(r0), "=r"(r1), "=r"(r2), "=r"(r3) : "r"(addr));
}
__device__ __forceinline__ void mma16816(float* c, unsigned a0, unsigned a1,
                                         unsigned a2, unsigned a3,
                                         unsigned b0, unsigned b1) {
    asm volatile(
        "mma.sync.aligned.m16n8k16.row.col.f32.bf16.bf16.f32 "
        "{%0,%1,%2,%3},{%4,%5,%6,%7},{%8,%9},{%0,%1,%2,%3};"
        : "+f"(c[0]), "+f"(c[1]), "+f"(c[2]), "+f"(c[3])
        : "r"(a0), "r"(a1), "r"(a2), "r"(a3), "r"(b0), "r"(b1));
}

// =====================================================================
// Kernel A: h = x @ W^T + b ; emit fp32 h and split-bf16 h in [head][j][d]
// =====================================================================
__global__ __launch_bounds__(256) void gemm_h_kernel(
    const float* __restrict__ x, const float* __restrict__ W,
    const float* __restrict__ b) {
    __shared__ float xs[128][36];
    __shared__ float ws[32][68];
    const int tid = threadIdx.x;
    const int tm = tid >> 4;
    const int tn = tid & 15;
    const int m0 = blockIdx.x * 128;
    const int hd = blockIdx.y;
    const int n0 = hd * 64;

    float acc[8][4];
#pragma unroll
    for (int r = 0; r < 8; r++)
#pragma unroll
        for (int c = 0; c < 4; c++) acc[r][c] = 0.f;

    for (int kb = 0; kb < INF; kb += 32) {
#pragma unroll
        for (int p = 0; p < 4; p++) {
            int idx = tid + p * 256;
            int m = idx >> 3, k4 = idx & 7;
            float4 v = *(const float4*)&x[(m0 + m) * INF + kb + k4 * 4];
            *(float4*)&xs[m][k4 * 4] = v;
        }
#pragma unroll
        for (int p = 0; p < 2; p++) {
            int idx = tid + p * 256;
            int n = idx >> 3, k4 = idx & 7;
            float4 v = *(const float4*)&W[(n0 + n) * INF + kb + k4 * 4];
            ws[k4 * 4 + 0][n] = v.x;
            ws[k4 * 4 + 1][n] = v.y;
            ws[k4 * 4 + 2][n] = v.z;
            ws[k4 * 4 + 3][n] = v.w;
        }
        __syncthreads();
#pragma unroll 8
        for (int k = 0; k < 32; k++) {
            float a[8];
#pragma unroll
            for (int r = 0; r < 8; r++) a[r] = xs[tm * 8 + r][k];
            float4 bv = *(const float4*)&ws[k][tn * 4];
#pragma unroll
            for (int r = 0; r < 8; r++) {
                acc[r][0] += a[r] * bv.x;
                acc[r][1] += a[r] * bv.y;
                acc[r][2] += a[r] * bv.z;
                acc[r][3] += a[r] * bv.w;
            }
        }
        __syncthreads();
    }
    float4 bias = *(const float4*)&b[n0 + tn * 4];
    float bc[4] = {bias.x, bias.y, bias.z, bias.w};
#pragma unroll
    for (int r = 0; r < 8; r++) {
        float v0 = acc[r][0] + bc[0];
        float v1 = acc[r][1] + bc[1];
        float v2 = acc[r][2] + bc[2];
        float v3 = acc[r][3] + bc[3];
        int m = m0 + tm * 8 + r;
        *(float4*)&g_h[m * OUTF + n0 + tn * 4] = make_float4(v0, v1, v2, v3);
        // split bf16, d-pairs
        unsigned u0 = pack_bf16x2(v1, v0);
        unsigned u1 = pack_bf16x2(v3, v2);
        float f00 = __uint_as_float(u0 << 16);
        float f01 = __uint_as_float(u0 & 0xffff0000u);
        float f10 = __uint_as_float(u1 << 16);
        float f11 = __uint_as_float(u1 & 0xffff0000u);
        unsigned l0 = pack_bf16x2(v1 - f01, v0 - f00);
        unsigned l1 = pack_bf16x2(v3 - f11, v2 - f10);
        size_t base = (size_t)(hd * NN + m) * 64 + tn * 4;
        *(uint2*)&g_hb_hi[base] = make_uint2(u0, u1);
        *(uint2*)&g_hb_lo[base] = make_uint2(l0, l1);
    }
}

// =====================================================================
// Kernel B: attention params
// =====================================================================
__global__ __launch_bounds__(256) void param_kernel(const float* __restrict__ aw) {
    const int tid = threadIdx.x;
    const int gw = blockIdx.x * 8 + (tid >> 5);
    const int lane = tid & 31;
    const int i = gw >> 3;
    const int hd = gw & 7;
    if (i >= NN) return;
    float h0 = g_h[i * OUTF + hd * 64 + lane];
    float h1 = g_h[i * OUTF + hd * 64 + lane + 32];
    float w00 = aw[hd * 128 + lane * 2 + 0];
    float w01 = aw[hd * 128 + lane * 2 + 1];
    float w10 = aw[hd * 128 + (lane + 32) * 2 + 0];
    float w11 = aw[hd * 128 + (lane + 32) * 2 + 1];
    float a0 = h0 * w00 + h1 * w10;
    float a1 = h0 * w01 + h1 * w11;
#pragma unroll
    for (int o = 16; o > 0; o >>= 1) {
        a0 += __shfl_xor_sync(0xffffffffu, a0, o);
        a1 += __shfl_xor_sync(0xffffffffu, a1, o);
    }
    if (lane == 0) {
        float4 ai, aj;
        ai.x = expf(a0);
        ai.y = expf(0.2f * a0);
        ai.z = -a0;
        ai.w = 0.f;
        aj.x = a1;
        aj.y = expf(a1);
        aj.z = expf(0.2f * a1);
        aj.w = 0.f;
        g_ai[hd * NN + i] = ai;
        g_aj[hd * NN + i] = aj;
    }
}

// =====================================================================
// Kernel C: adj -> bitmask
// =====================================================================
__global__ __launch_bounds__(256) void bits_kernel(const int* __restrict__ adj) {
    const int gw = blockIdx.x * 8 + (threadIdx.x >> 5);
    const int lane = threadIdx.x & 31;
    const int i = gw / NW;
    const int jw = gw % NW;
    if (i >= NN) return;
    int v = adj[i * NN + jw * 32 + lane];
    unsigned m = __ballot_sync(0xffffffffu, v > 0);
    if (lane == 0) g_bits[i * NW + jw] = m;
}

// =====================================================================
// Kernel D: HMMA (mma.sync bf16) attention.  Grid (48, 8), 256 threads.
// Per warp: 16 rows. E built directly in A-fragment registers (hi/lo).
// B = h tile [64j x 64d] bf16 hi/lo staged via cp.async, XOR-swizzled,
// loaded with ldmatrix.x4.trans. 3 products: EhBh + EhBl + ElBh.
// =====================================================================
__global__ __launch_bounds__(256, 2) void attn_kernel(float* __restrict__ out) {
    __shared__ __align__(16) char   sB[2][2][8192];   // [stage][hi/lo][64j*128B]
    __shared__ __align__(16) float4 sAj[2][64];

    const int tid = threadIdx.x;
    const int wid = tid >> 5;
    const int lane = tid & 31;
    const int hd = blockIdx.y;
    const int i0 = blockIdx.x * 128;
    const int gr = lane >> 2;         // row within 8-row group
    const int qc = (lane & 3) * 2;    // k-pair base
    const int mb = wid * 16;

    const uint32_t smB = smem_u32(&sB[0][0][0]);
    const uint32_t smA = smem_u32(&sAj[0][0]);

    // cp.async staging identity: chunk = (j = tid>>3, c = tid&7), 16B each
    const int sj = tid >> 3, sc = tid & 7;
    const uint32_t sdst = (uint32_t)(sj * 128 + ((sc ^ (sj & 7)) << 4));
    const char* srcH = (const char*)(g_hb_hi + (size_t)hd * NN * 64);
    const char* srcL = (const char*)(g_hb_lo + (size_t)hd * NN * 64);

    // ldmatrix lane identity
    const int lg = lane >> 3, lr = lane & 7;
    const int joff = (lg & 1) * 8 + lr;
    const int nsel = lg >> 1;
    const uint32_t lmb = (uint32_t)(joff * 128);
    const int jm = joff & 7;

    // per-row params
    const float4 aiL = g_ai[hd * NN + i0 + mb + gr];
    const float4 aiH = g_ai[hd * NN + i0 + mb + gr + 8];
    const uint2* mrow0 = (const uint2*)(g_bits + (size_t)(i0 + mb + gr) * NW);
    const uint2* mrow1 = (const uint2*)(g_bits + (size_t)(i0 + mb + gr + 8) * NW);

    float acc[8][4];
#pragma unroll
    for (int n = 0; n < 8; n++)
#pragma unroll
        for (int c = 0; c < 4; c++) acc[n][c] = 0.f;
    float lac0 = 0.f, lac1 = 0.f;

    // prologue: stage tile 0 into stage 0
    {
        size_t go = (size_t)tid * 16;
        uint32_t bh = smB, bl = smB + 8192;
        cp16(bh + sdst, srcH + go);
        cp16(bh + sdst + 4096, srcH + go + 4096);
        cp16(bl + sdst, srcL + go);
        cp16(bl + sdst + 4096, srcL + go + 4096);
        if (tid < 64) cp16(smA + tid * 16, &g_aj[hd * NN + tid]);
        asm volatile("cp.async.commit_group;" ::: "memory");
    }

#pragma unroll 1
    for (int jt = 0; jt < NN / 64; jt++) {
        const int s = jt & 1;
        if (jt + 1 < NN / 64) {
            size_t go = (size_t)(jt + 1) * 8192 + tid * 16;
            uint32_t bh = smB + (s ^ 1) * 16384, bl = bh + 8192;
            cp16(bh + sdst, srcH + go);
            cp16(bh + sdst + 4096, srcH + go + 4096);
            cp16(bl + sdst, srcL + go);
            cp16(bl + sdst + 4096, srcL + go + 4096);
            if (tid < 64) cp16(smA + (s ^ 1) * 1024 + tid * 16,
                               &g_aj[hd * NN + (jt + 1) * 64 + tid]);
            asm volatile("cp.async.commit_group;" ::: "memory");
            asm volatile("cp.async.wait_group 1;" ::: "memory");
        } else {
            asm volatile("cp.async.wait_group 0;" ::: "memory");
        }
        __syncthreads();

        const uint32_t bh = smB + s * 16384;
        const uint32_t bl = bh + 8192;
        const float4* ajb = &sAj[s][0];

        const uint2 M0 = mrow0[jt];
        const uint2 M1 = mrow1[jt];
        unsigned mk0[4] = {M0.x & 0xffffu, M0.x >> 16, M0.y & 0xffffu, M0.y >> 16};
        unsigned mk1[4] = {M1.x & 0xffffu, M1.x >> 16, M1.y & 0xffffu, M1.y >> 16};

#pragma unroll
        for (int kk = 0; kk < 4; kk++) {
            float4 aj0 = ajb[kk * 16 + qc];
            float4 aj1 = ajb[kk * 16 + qc + 1];
            float4 aj8 = ajb[kk * 16 + qc + 8];
            float4 aj9 = ajb[kk * 16 + qc + 9];
            unsigned mm0 = mk0[kk], mm1 = mk1[kk];

            float e00 = (aj0.x > aiL.z) ? (aiL.x * aj0.y) : (aiL.y * aj0.z);
            float e01 = (aj1.x > aiL.z) ? (aiL.x * aj1.y) : (aiL.y * aj1.z);
            float e08 = (aj8.x > aiL.z) ? (aiL.x * aj8.y) : (aiL.y * aj8.z);
            float e09 = (aj9.x > aiL.z) ? (aiL.x * aj9.y) : (aiL.y * aj9.z);
            float e10 = (aj0.x > aiH.z) ? (aiH.x * aj0.y) : (aiH.y * aj0.z);
            float e11 = (aj1.x > aiH.z) ? (aiH.x * aj1.y) : (aiH.y * aj1.z);
            float e18 = (aj8.x > aiH.z) ? (aiH.x * aj8.y) : (aiH.y * aj8.z);
            float e19 = (aj9.x > aiH.z) ? (aiH.x * aj9.y) : (aiH.y * aj9.z);
            e00 = ((mm0 >> qc) & 1u) ? e00 : 0.f;
            e01 = ((mm0 >> (qc + 1)) & 1u) ? e01 : 0.f;
            e08 = ((mm0 >> (qc + 8)) & 1u) ? e08 : 0.f;
            e09 = ((mm0 >> (qc + 9)) & 1u) ? e09 : 0.f;
            e10 = ((mm1 >> qc) & 1u) ? e10 : 0.f;
            e11 = ((mm1 >> (qc + 1)) & 1u) ? e11 : 0.f;
            e18 = ((mm1 >> (qc + 8)) & 1u) ? e18 : 0.f;
            e19 = ((mm1 >> (qc + 9)) & 1u) ? e19 : 0.f;
            lac0 += (e00 + e01) + (e08 + e09);
            lac1 += (e10 + e11) + (e18 + e19);

            unsigned ah0 = pack_bf16x2(e01, e00);
            unsigned ah1 = pack_bf16x2(e11, e10);
            unsigned ah2 = pack_bf16x2(e09, e08);
            unsigned ah3 = pack_bf16x2(e19, e18);
            unsigned al0, al1, al2, al3;
            {
                float f0 = __uint_as_float(ah0 << 16), f1 = __uint_as_float(ah0 & 0xffff0000u);
                al0 = pack_bf16x2(e01 - f1, e00 - f0);
                f0 = __uint_as_float(ah1 << 16); f1 = __uint_as_float(ah1 & 0xffff0000u);
                al1 = pack_bf16x2(e11 - f1, e10 - f0);
                f0 = __uint_as_float(ah2 << 16); f1 = __uint_as_float(ah2 & 0xffff0000u);
                al2 = pack_bf16x2(e09 - f1, e08 - f0);
                f0 = __uint_as_float(ah3 << 16); f1 = __uint_as_float(ah3 & 0xffff0000u);
                al3 = pack_bf16x2(e19 - f1, e18 - f0);
            }

#pragma unroll
            for (int nh = 0; nh < 2; nh++) {
                const int nb0 = nh * 32, nb1 = nh * 32 + 16;
                uint32_t a0 = bh + kk * 2048 + lmb + ((((nb0 >> 3) + nsel) ^ jm) << 4);
                uint32_t a1 = bh + kk * 2048 + lmb + ((((nb1 >> 3) + nsel) ^ jm) << 4);
                uint32_t a2 = bl + kk * 2048 + lmb + ((((nb0 >> 3) + nsel) ^ jm) << 4);
                uint32_t a3 = bl + kk * 2048 + lmb + ((((nb1 >> 3) + nsel) ^ jm) << 4);
                unsigned t[8], u[8];
                ldm4t(a0, t[0], t[1], t[2], t[3]);
                ldm4t(a1, t[4], t[5], t[6], t[7]);
                ldm4t(a2, u[0], u[1], u[2], u[3]);
                ldm4t(a3, u[4], u[5], u[6], u[7]);
#pragma unroll
                for (int q = 0; q < 4; q++) {
                    float* C = acc[nh * 4 + q];
                    mma16816(C, ah0, ah1, ah2, ah3, t[2 * q], t[2 * q + 1]);
                    mma16816(C, ah0, ah1, ah2, ah3, u[2 * q], u[2 * q + 1]);
                    mma16816(C, al0, al1, al2, al3, t[2 * q], t[2 * q + 1]);
                }
            }
        }
        __syncthreads();
    }

    // ---- row-sum reduction across the 4 lanes of each row group ----
#pragma unroll
    for (int off = 1; off <= 2; off <<= 1) {
        lac0 += __shfl_xor_sync(0xffffffffu, lac0, off);
        lac1 += __shfl_xor_sync(0xffffffffu, lac1, off);
    }
    float inv0 = (lac0 > 0.f) ? (1.0f / lac0) : 0.f;
    float inv1 = (lac1 > 0.f) ? (1.0f / lac1) : 0.f;

    float* b0 = out + (size_t)(i0 + mb + gr) * OUTF + hd * 64 + qc;
    float* b1 = out + (size_t)(i0 + mb + gr + 8) * OUTF + hd * 64 + qc;
#pragma unroll
    for (int nt = 0; nt < 8; nt++) {
        *(float2*)(b0 + nt * 8) = make_float2(acc[nt][0] * inv0, acc[nt][1] * inv0);
        *(float2*)(b1 + nt * 8) = make_float2(acc[nt][2] * inv1, acc[nt][3] * inv1);
    }
}

// =====================================================================
extern "C" void kernel_launch(void* const* d_in, const int* in_sizes, int n_in,
                              void* d_out, int out_size) {
    const float* x = (const float*)d_in[0];
    const int* adj = (const int*)d_in[1];
    const float* W = (const float*)d_in[2];
    const float* b = (const float*)d_in[3];
    const float* aw = (const float*)d_in[4];
    float* out = (float*)d_out;

    gemm_h_kernel<<<dim3(NN / 128, H), 256>>>(x, W, b);
    param_kernel<<<(NN * H) / 8, 256>>>(aw);
    bits_kernel<<<(NN * NW) / 8, 256>>>(adj);
    attn_kernel<<<dim3(NN / 128, H), 256>>>(out);
}

// round 6
// speedup vs baseline: 3.4258x; 1.1731x over previous
#include <cuda_runtime.h>
#include <cuda_bf16.h>
#include <cuda_fp16.h>
#include <cstdint>

#define NN   6144
#define INF  512
#define H    8
#define OUTF 512
#define NW   192
#define ECAP 28000.0f

// ---------------- scratch ----------------
__device__ __align__(16) float    g_h[NN * OUTF];
__device__ __align__(16) float2   g_a0a1[H * NN];
__device__ __align__(16) float4   g_ai[H * NN];            // {u', u5', -a0, 0}
__device__ __align__(16) float4   g_aj[H * NN];            // {a1, v, v5, 0}
__device__ unsigned g_a1max[H];                            // orderable keys
__device__ __align__(16) unsigned g_bits[NN * NW];
__device__ __align__(16) __half   g_hb_hi[H * NN * 64];    // [head][j][d]
__device__ __align__(16) __half   g_hb_lo[H * NN * 64];

// ---------------- helpers ----------------
__device__ __forceinline__ unsigned pack_f16x2(float hi, float lo) {
    unsigned r;
    asm("cvt.rn.f16x2.f32 %0, %1, %2;" : "=r"(r) : "f"(hi), "f"(lo));
    return r;
}
__device__ __forceinline__ uint32_t smem_u32(const void* p) {
    uint32_t a;
    asm("{ .reg .u64 t; cvta.to.shared.u64 t, %1; cvt.u32.u64 %0, t; }" : "=r"(a) : "l"(p));
    return a;
}
__device__ __forceinline__ void cp16(uint32_t dst, const void* src) {
    asm volatile("cp.async.cg.shared.global [%0], [%1], 16;" :: "r"(dst), "l"(src));
}
__device__ __forceinline__ void ldm4t(uint32_t addr, unsigned& r0, unsigned& r1,
                                      unsigned& r2, unsigned& r3) {
    asm volatile("ldmatrix.sync.aligned.m8n8.x4.trans.shared.b16 {%0,%1,%2,%3}, [%4];"
                 : "=r"(r0), "=r"(r1), "=r"(r2), "=r"(r3) : "r"(addr));
}
__device__ __forceinline__ void mma16816(float* c, unsigned a0, unsigned a1,
                                         unsigned a2, unsigned a3,
                                         unsigned b0, unsigned b1) {
    asm volatile(
        "mma.sync.aligned.m16n8k16.row.col.f32.f16.f16.f32 "
        "{%0,%1,%2,%3},{%4,%5,%6,%7},{%8,%9},{%0,%1,%2,%3};"
        : "+f"(c[0]), "+f"(c[1]), "+f"(c[2]), "+f"(c[3])
        : "r"(a0), "r"(a1), "r"(a2), "r"(a3), "r"(b0), "r"(b1));
}
__device__ __forceinline__ unsigned fkey(float f) {
    unsigned b = __float_as_uint(f);
    return (b & 0x80000000u) ? ~b : (b | 0x80000000u);
}
__device__ __forceinline__ float funkey(unsigned k) {
    unsigned b = (k & 0x80000000u) ? (k & 0x7fffffffu) : ~k;
    return __uint_as_float(b);
}

// =====================================================================
// Kernel 0: reset per-head a1max keys (must run every launch)
// =====================================================================
__global__ void init_kernel() {
    if (threadIdx.x < H) g_a1max[threadIdx.x] = 0u;
}

// =====================================================================
// Kernel A: h = x @ W^T + b ; emit fp32 h and split-fp16 h in [head][j][d]
// =====================================================================
__global__ __launch_bounds__(256) void gemm_h_kernel(
    const float* __restrict__ x, const float* __restrict__ W,
    const float* __restrict__ b) {
    __shared__ float xs[128][36];
    __shared__ float ws[32][68];
    const int tid = threadIdx.x;
    const int tm = tid >> 4;
    const int tn = tid & 15;
    const int m0 = blockIdx.x * 128;
    const int hd = blockIdx.y;
    const int n0 = hd * 64;

    float acc[8][4];
#pragma unroll
    for (int r = 0; r < 8; r++)
#pragma unroll
        for (int c = 0; c < 4; c++) acc[r][c] = 0.f;

    for (int kb = 0; kb < INF; kb += 32) {
#pragma unroll
        for (int p = 0; p < 4; p++) {
            int idx = tid + p * 256;
            int m = idx >> 3, k4 = idx & 7;
            float4 v = *(const float4*)&x[(m0 + m) * INF + kb + k4 * 4];
            *(float4*)&xs[m][k4 * 4] = v;
        }
#pragma unroll
        for (int p = 0; p < 2; p++) {
            int idx = tid + p * 256;
            int n = idx >> 3, k4 = idx & 7;
            float4 v = *(const float4*)&W[(n0 + n) * INF + kb + k4 * 4];
            ws[k4 * 4 + 0][n] = v.x;
            ws[k4 * 4 + 1][n] = v.y;
            ws[k4 * 4 + 2][n] = v.z;
            ws[k4 * 4 + 3][n] = v.w;
        }
        __syncthreads();
#pragma unroll 8
        for (int k = 0; k < 32; k++) {
            float a[8];
#pragma unroll
            for (int r = 0; r < 8; r++) a[r] = xs[tm * 8 + r][k];
            float4 bv = *(const float4*)&ws[k][tn * 4];
#pragma unroll
            for (int r = 0; r < 8; r++) {
                acc[r][0] += a[r] * bv.x;
                acc[r][1] += a[r] * bv.y;
                acc[r][2] += a[r] * bv.z;
                acc[r][3] += a[r] * bv.w;
            }
        }
        __syncthreads();
    }
    float4 bias = *(const float4*)&b[n0 + tn * 4];
    float bc[4] = {bias.x, bias.y, bias.z, bias.w};
#pragma unroll
    for (int r = 0; r < 8; r++) {
        float v[4];
#pragma unroll
        for (int c = 0; c < 4; c++) v[c] = acc[r][c] + bc[c];
        int m = m0 + tm * 8 + r;
        *(float4*)&g_h[m * OUTF + n0 + tn * 4] = make_float4(v[0], v[1], v[2], v[3]);
        // split fp16
        __half hh[4], hl[4];
#pragma unroll
        for (int c = 0; c < 4; c++) {
            hh[c] = __float2half_rn(v[c]);
            hl[c] = __float2half_rn(v[c] - __half2float(hh[c]));
        }
        size_t base = (size_t)(hd * NN + m) * 64 + tn * 4;
        unsigned u0 = ((unsigned)__half_as_ushort(hh[1]) << 16) | __half_as_ushort(hh[0]);
        unsigned u1 = ((unsigned)__half_as_ushort(hh[3]) << 16) | __half_as_ushort(hh[2]);
        unsigned l0 = ((unsigned)__half_as_ushort(hl[1]) << 16) | __half_as_ushort(hl[0]);
        unsigned l1 = ((unsigned)__half_as_ushort(hl[3]) << 16) | __half_as_ushort(hl[2]);
        *(uint2*)&g_hb_hi[base] = make_uint2(u0, u1);
        *(uint2*)&g_hb_lo[base] = make_uint2(l0, l1);
    }
}

// =====================================================================
// Kernel B1: a0/a1 per (head,node) + per-head a1max
// =====================================================================
__global__ __launch_bounds__(256) void param1_kernel(const float* __restrict__ aw) {
    const int tid = threadIdx.x;
    const int gw = blockIdx.x * 8 + (tid >> 5);
    const int lane = tid & 31;
    const int i = gw >> 3;
    const int hd = gw & 7;
    if (i >= NN) return;
    float h0 = g_h[i * OUTF + hd * 64 + lane];
    float h1 = g_h[i * OUTF + hd * 64 + lane + 32];
    float w00 = aw[hd * 128 + lane * 2 + 0];
    float w01 = aw[hd * 128 + lane * 2 + 1];
    float w10 = aw[hd * 128 + (lane + 32) * 2 + 0];
    float w11 = aw[hd * 128 + (lane + 32) * 2 + 1];
    float a0 = h0 * w00 + h1 * w10;
    float a1 = h0 * w01 + h1 * w11;
#pragma unroll
    for (int o = 16; o > 0; o >>= 1) {
        a0 += __shfl_xor_sync(0xffffffffu, a0, o);
        a1 += __shfl_xor_sync(0xffffffffu, a1, o);
    }
    if (lane == 0) {
        g_a0a1[hd * NN + i] = make_float2(a0, a1);
        atomicMax(&g_a1max[hd], fkey(a1));
    }
}

// =====================================================================
// Kernel B2: build scaled exp tables (fp16-safe E range)
// =====================================================================
__global__ __launch_bounds__(256) void param2_kernel() {
    int g = blockIdx.x * 256 + threadIdx.x;      // g = hd*NN + i
    if (g >= H * NN) return;
    int hd = g / NN;
    float2 a = g_a0a1[g];
    float a1max = funkey(g_a1max[hd]);
    float z = a.x + a1max;
    float sl = (z > 0.f) ? z : 0.2f * z;
    float4 ai, aj;
    ai.x = ECAP * expf(a.x - sl);          // u'
    ai.y = ECAP * expf(0.2f * a.x - sl);   // u5'
    ai.z = -a.x;
    ai.w = 0.f;
    aj.x = a.y;
    aj.y = expf(a.y);
    aj.z = expf(0.2f * a.y);
    aj.w = 0.f;
    g_ai[g] = ai;
    g_aj[g] = aj;
}

// =====================================================================
// Kernel C: adj -> bitmask
// =====================================================================
__global__ __launch_bounds__(256) void bits_kernel(const int* __restrict__ adj) {
    const int gw = blockIdx.x * 8 + (threadIdx.x >> 5);
    const int lane = threadIdx.x & 31;
    const int i = gw / NW;
    const int jw = gw % NW;
    if (i >= NN) return;
    int v = adj[i * NN + jw * 32 + lane];
    unsigned m = __ballot_sync(0xffffffffu, v > 0);
    if (lane == 0) g_bits[i * NW + jw] = m;
}

// =====================================================================
// Kernel D: fp16 HMMA attention. Grid (48, 8), 128 threads, 4 warps.
// M=32 rows/warp (2 A-frags share B-frag loads). 2 products: E*(Bh) + E*(Bl).
// =====================================================================
__global__ __launch_bounds__(128, 3) void attn_kernel(float* __restrict__ out) {
    __shared__ __align__(16) char   sB[2][2][8192];   // [stage][hi/lo][64j*128B]
    __shared__ __align__(16) float4 sAj[2][64];

    const int tid = threadIdx.x;
    const int wid = tid >> 5;
    const int lane = tid & 31;
    const int hd = blockIdx.y;
    const int i0 = blockIdx.x * 128;
    const int gr = lane >> 2;
    const int qc = (lane & 3) * 2;
    const int mb = wid * 32;

    const uint32_t smB = smem_u32(&sB[0][0][0]);
    const uint32_t smA = smem_u32(&sAj[0][0]);

    // cp.async staging: 4 chunks per thread per 8KB buffer
    uint32_t sdst[4];
#pragma unroll
    for (int p = 0; p < 4; p++) {
        int idx = tid + p * 128;
        int sj = idx >> 3, sc = idx & 7;
        sdst[p] = (uint32_t)(sj * 128 + ((sc ^ (sj & 7)) << 4));
    }
    const char* srcH = (const char*)(g_hb_hi + (size_t)hd * NN * 64);
    const char* srcL = (const char*)(g_hb_lo + (size_t)hd * NN * 64);

    // ldmatrix lane identity
    const int lg = lane >> 3, lr = lane & 7;
    const int joff = (lg & 1) * 8 + lr;
    const int nsel = lg >> 1;
    const uint32_t lmb = (uint32_t)(joff * 128);
    const int jm = joff & 7;

    // per-row params: 4 fragment rows
    float4 ai[4];
#pragma unroll
    for (int r = 0; r < 4; r++) ai[r] = g_ai[hd * NN + i0 + mb + gr + r * 8];
    const uint2* mrow[4];
#pragma unroll
    for (int r = 0; r < 4; r++)
        mrow[r] = (const uint2*)(g_bits + (size_t)(i0 + mb + gr + r * 8) * NW);

    float accA[8][4], accB[8][4];
#pragma unroll
    for (int n = 0; n < 8; n++)
#pragma unroll
        for (int c = 0; c < 4; c++) { accA[n][c] = 0.f; accB[n][c] = 0.f; }
    float lacc[4] = {0.f, 0.f, 0.f, 0.f};

    // prologue: stage tile 0
    {
        uint32_t bh = smB, bl = smB + 8192;
#pragma unroll
        for (int p = 0; p < 4; p++) {
            size_t go = (size_t)(tid + p * 128) * 16;
            cp16(bh + sdst[p], srcH + go);
            cp16(bl + sdst[p], srcL + go);
        }
        if (tid < 64) cp16(smA + tid * 16, &g_aj[hd * NN + tid]);
        asm volatile("cp.async.commit_group;" ::: "memory");
    }

#pragma unroll 1
    for (int jt = 0; jt < NN / 64; jt++) {
        const int s = jt & 1;

        // prefetch masks for this tile before any waiting
        uint2 M[4];
#pragma unroll
        for (int r = 0; r < 4; r++) M[r] = mrow[r][jt];

        if (jt + 1 < NN / 64) {
            uint32_t bh = smB + (s ^ 1) * 16384, bl = bh + 8192;
#pragma unroll
            for (int p = 0; p < 4; p++) {
                size_t go = (size_t)(jt + 1) * 8192 + (size_t)(tid + p * 128) * 16;
                cp16(bh + sdst[p], srcH + go);
                cp16(bl + sdst[p], srcL + go);
            }
            if (tid < 64) cp16(smA + (s ^ 1) * 1024 + tid * 16,
                               &g_aj[hd * NN + (jt + 1) * 64 + tid]);
            asm volatile("cp.async.commit_group;" ::: "memory");
            asm volatile("cp.async.wait_group 1;" ::: "memory");
        } else {
            asm volatile("cp.async.wait_group 0;" ::: "memory");
        }
        __syncthreads();

        const uint32_t bh = smB + s * 16384;
        const uint32_t bl = bh + 8192;
        const float4* ajb = &sAj[s][0];

        unsigned mk[4][4];
#pragma unroll
        for (int r = 0; r < 4; r++) {
            mk[r][0] = M[r].x & 0xffffu;
            mk[r][1] = M[r].x >> 16;
            mk[r][2] = M[r].y & 0xffffu;
            mk[r][3] = M[r].y >> 16;
        }

#pragma unroll
        for (int kk = 0; kk < 4; kk++) {
            float4 aj0 = ajb[kk * 16 + qc];
            float4 aj1 = ajb[kk * 16 + qc + 1];
            float4 aj8 = ajb[kk * 16 + qc + 8];
            float4 aj9 = ajb[kk * 16 + qc + 9];

            // E for 4 fragment rows x 4 j
            unsigned ah[4][2];   // [row r][k-half]
#pragma unroll
            for (int r = 0; r < 4; r++) {
                float4 a = ai[r];
                unsigned mm = mk[r][kk];
                float e0 = (aj0.x > a.z) ? (a.x * aj0.y) : (a.y * aj0.z);
                float e1 = (aj1.x > a.z) ? (a.x * aj1.y) : (a.y * aj1.z);
                float e8 = (aj8.x > a.z) ? (a.x * aj8.y) : (a.y * aj8.z);
                float e9 = (aj9.x > a.z) ? (a.x * aj9.y) : (a.y * aj9.z);
                e0 = ((mm >> qc) & 1u) ? e0 : 0.f;
                e1 = ((mm >> (qc + 1)) & 1u) ? e1 : 0.f;
                e8 = ((mm >> (qc + 8)) & 1u) ? e8 : 0.f;
                e9 = ((mm >> (qc + 9)) & 1u) ? e9 : 0.f;
                lacc[r] += (e0 + e1) + (e8 + e9);
                ah[r][0] = pack_f16x2(e1, e0);
                ah[r][1] = pack_f16x2(e9, e8);
            }

#pragma unroll
            for (int nh = 0; nh < 2; nh++) {
                const int nb0 = nh * 32, nb1 = nh * 32 + 16;
                uint32_t a0 = bh + kk * 2048 + lmb + ((((nb0 >> 3) + nsel) ^ jm) << 4);
                uint32_t a1 = bh + kk * 2048 + lmb + ((((nb1 >> 3) + nsel) ^ jm) << 4);
                uint32_t a2 = bl + kk * 2048 + lmb + ((((nb0 >> 3) + nsel) ^ jm) << 4);
                uint32_t a3 = bl + kk * 2048 + lmb + ((((nb1 >> 3) + nsel) ^ jm) << 4);
                unsigned t[8], u[8];
                ldm4t(a0, t[0], t[1], t[2], t[3]);
                ldm4t(a1, t[4], t[5], t[6], t[7]);
                ldm4t(a2, u[0], u[1], u[2], u[3]);
                ldm4t(a3, u[4], u[5], u[6], u[7]);
#pragma unroll
                for (int q = 0; q < 4; q++) {
                    float* CA = accA[nh * 4 + q];
                    float* CB = accB[nh * 4 + q];
                    mma16816(CA, ah[0][0], ah[1][0], ah[0][1], ah[1][1], t[2 * q], t[2 * q + 1]);
                    mma16816(CA, ah[0][0], ah[1][0], ah[0][1], ah[1][1], u[2 * q], u[2 * q + 1]);
                    mma16816(CB, ah[2][0], ah[3][0], ah[2][1], ah[3][1], t[2 * q], t[2 * q + 1]);
                    mma16816(CB, ah[2][0], ah[3][0], ah[2][1], ah[3][1], u[2 * q], u[2 * q + 1]);
                }
            }
        }
        __syncthreads();
    }

    // row-sum reduction across the 4 lanes of each row group
#pragma unroll
    for (int off = 1; off <= 2; off <<= 1)
#pragma unroll
        for (int r = 0; r < 4; r++)
            lacc[r] += __shfl_xor_sync(0xffffffffu, lacc[r], off);
    float inv[4];
#pragma unroll
    for (int r = 0; r < 4; r++) inv[r] = (lacc[r] > 0.f) ? (1.0f / lacc[r]) : 0.f;

#pragma unroll
    for (int f = 0; f < 2; f++) {
        float (*A)[4] = f ? accB : accA;
        float* b0 = out + (size_t)(i0 + mb + gr + f * 16) * OUTF + hd * 64 + qc;
        float* b1 = out + (size_t)(i0 + mb + gr + f * 16 + 8) * OUTF + hd * 64 + qc;
        float i0v = inv[f * 2], i1v = inv[f * 2 + 1];
#pragma unroll
        for (int nt = 0; nt < 8; nt++) {
            *(float2*)(b0 + nt * 8) = make_float2(A[nt][0] * i0v, A[nt][1] * i0v);
            *(float2*)(b1 + nt * 8) = make_float2(A[nt][2] * i1v, A[nt][3] * i1v);
        }
    }
}

// =====================================================================
extern "C" void kernel_launch(void* const* d_in, const int* in_sizes, int n_in,
                              void* d_out, int out_size) {
    const float* x = (const float*)d_in[0];
    const int* adj = (const int*)d_in[1];
    const float* W = (const float*)d_in[2];
    const float* b = (const float*)d_in[3];
    const float* aw = (const float*)d_in[4];
    float* out = (float*)d_out;

    init_kernel<<<1, 32>>>();
    gemm_h_kernel<<<dim3(NN / 128, H), 256>>>(x, W, b);
    param1_kernel<<<(NN * H) / 8, 256>>>(aw);
    param2_kernel<<<(H * NN + 255) / 256, 256>>>();
    bits_kernel<<<(NN * NW) / 8, 256>>>(adj);
    attn_kernel<<<dim3(NN / 128, H), 128>>>(out);
}

// round 7
// speedup vs baseline: 4.7726x; 1.3931x over previous
#include <cuda_runtime.h>
#include <cuda_fp16.h>
#include <cstdint>

#define NN   6144
#define INF  512
#define H    8
#define OUTF 512
#define NW   192
#define ECAP 28000.0f

// ---------------- scratch ----------------
__device__ __align__(16) float    g_h[NN * OUTF];
__device__ __align__(16) float2   g_a0a1[H * NN];
__device__ __align__(16) float4   g_ai[H * NN];            // {u', u5', -a0, 0}
__device__ __align__(16) float4   g_aj[H * NN];            // {a1, v, v5, 0}
__device__ unsigned g_a1max[H];
__device__ __align__(16) unsigned g_bits[NN * NW];
__device__ __align__(16) __half   g_hb[H * NN * 64];       // [head][j][d] fp16
__device__ __align__(16) __half   g_xh[NN * INF];
__device__ __align__(16) __half   g_xl[NN * INF];
__device__ __align__(16) __half   g_wh[OUTF * INF];
__device__ __align__(16) __half   g_wl[OUTF * INF];

// ---------------- helpers ----------------
__device__ __forceinline__ unsigned pack_f16x2(float hi, float lo) {
    unsigned r;
    asm("cvt.rn.f16x2.f32 %0, %1, %2;" : "=r"(r) : "f"(hi), "f"(lo));
    return r;
}
__device__ __forceinline__ uint32_t smem_u32(const void* p) {
    uint32_t a;
    asm("{ .reg .u64 t; cvta.to.shared.u64 t, %1; cvt.u32.u64 %0, t; }" : "=r"(a) : "l"(p));
    return a;
}
__device__ __forceinline__ void cp16(uint32_t dst, const void* src) {
    asm volatile("cp.async.cg.shared.global [%0], [%1], 16;" :: "r"(dst), "l"(src));
}
__device__ __forceinline__ void ldm4(uint32_t addr, unsigned& r0, unsigned& r1,
                                     unsigned& r2, unsigned& r3) {
    asm volatile("ldmatrix.sync.aligned.m8n8.x4.shared.b16 {%0,%1,%2,%3}, [%4];"
                 : "=r"(r0), "=r"(r1), "=r"(r2), "=r"(r3) : "r"(addr));
}
__device__ __forceinline__ void ldm4t(uint32_t addr, unsigned& r0, unsigned& r1,
                                      unsigned& r2, unsigned& r3) {
    asm volatile("ldmatrix.sync.aligned.m8n8.x4.trans.shared.b16 {%0,%1,%2,%3}, [%4];"
                 : "=r"(r0), "=r"(r1), "=r"(r2), "=r"(r3) : "r"(addr));
}
__device__ __forceinline__ void mma16816(float* c, unsigned a0, unsigned a1,
                                         unsigned a2, unsigned a3,
                                         unsigned b0, unsigned b1) {
    asm volatile(
        "mma.sync.aligned.m16n8k16.row.col.f32.f16.f16.f32 "
        "{%0,%1,%2,%3},{%4,%5,%6,%7},{%8,%9},{%0,%1,%2,%3};"
        : "+f"(c[0]), "+f"(c[1]), "+f"(c[2]), "+f"(c[3])
        : "r"(a0), "r"(a1), "r"(a2), "r"(a3), "r"(b0), "r"(b1));
}
__device__ __forceinline__ unsigned fkey(float f) {
    unsigned b = __float_as_uint(f);
    return (b & 0x80000000u) ? ~b : (b | 0x80000000u);
}
__device__ __forceinline__ float funkey(unsigned k) {
    unsigned b = (k & 0x80000000u) ? (k & 0x7fffffffu) : ~k;
    return __uint_as_float(b);
}

// =====================================================================
// Kernel 0: reset per-head a1max keys
// =====================================================================
__global__ void init_kernel() {
    if (threadIdx.x < H) g_a1max[threadIdx.x] = 0u;
}

// =====================================================================
// Kernel CV: split x and W into fp16 hi/lo
// =====================================================================
__global__ __launch_bounds__(256) void cvt_kernel(const float* __restrict__ x,
                                                  const float* __restrict__ W) {
    int t = blockIdx.x * 256 + threadIdx.x;           // one float4 per thread
    const int NX = NN * INF / 4;
    const int NWW = OUTF * INF / 4;
    if (t < NX) {
        float4 v = *(const float4*)&x[t * 4];
        unsigned h0 = pack_f16x2(v.y, v.x);
        unsigned h1 = pack_f16x2(v.w, v.z);
        float r0 = v.x - __half2float(__ushort_as_half((unsigned short)(h0 & 0xffff)));
        float r1 = v.y - __half2float(__ushort_as_half((unsigned short)(h0 >> 16)));
        float r2 = v.z - __half2float(__ushort_as_half((unsigned short)(h1 & 0xffff)));
        float r3 = v.w - __half2float(__ushort_as_half((unsigned short)(h1 >> 16)));
        *(uint2*)&g_xh[t * 4] = make_uint2(h0, h1);
        *(uint2*)&g_xl[t * 4] = make_uint2(pack_f16x2(r1, r0), pack_f16x2(r3, r2));
    } else if (t < NX + NWW) {
        int u = t - NX;
        float4 v = *(const float4*)&W[u * 4];
        unsigned h0 = pack_f16x2(v.y, v.x);
        unsigned h1 = pack_f16x2(v.w, v.z);
        float r0 = v.x - __half2float(__ushort_as_half((unsigned short)(h0 & 0xffff)));
        float r1 = v.y - __half2float(__ushort_as_half((unsigned short)(h0 >> 16)));
        float r2 = v.z - __half2float(__ushort_as_half((unsigned short)(h1 & 0xffff)));
        float r3 = v.w - __half2float(__ushort_as_half((unsigned short)(h1 >> 16)));
        *(uint2*)&g_wh[u * 4] = make_uint2(h0, h1);
        *(uint2*)&g_wl[u * 4] = make_uint2(pack_f16x2(r1, r0), pack_f16x2(r3, r2));
    }
}

// =====================================================================
// Kernel A: HMMA h = x @ W^T + b  (3 products: xh*Wh + xl*Wh + xh*Wl)
// Grid (48, 8), 128 threads. Tile 128m x 64n, K stages of 32.
// smem per stage: xh 128x32 (pad 40) 10240B, xl 10240, wh 64x32 5120, wl 5120.
// =====================================================================
#define GX_ST 30720
#define GX_TOT (2 * GX_ST)

__global__ __launch_bounds__(128, 3) void gemm_h_kernel(
    const float* __restrict__ b) {
    extern __shared__ char gsm[];
    const uint32_t smb = smem_u32(gsm);
    const int tid = threadIdx.x;
    const int wid = tid >> 5;
    const int lane = tid & 31;
    const int m0 = blockIdx.x * 128;
    const int hd = blockIdx.y;
    const int n0 = hd * 64;
    const int wm = wid * 32;

    float acc[8][2][4];
#pragma unroll
    for (int f = 0; f < 8; f++)
#pragma unroll
        for (int m = 0; m < 2; m++)
#pragma unroll
            for (int c = 0; c < 4; c++) acc[f][m][c] = 0.f;

    // staging identities
    const int xrow = tid >> 2, xch = tid & 3;        // +p*32 rows
    // A ldmatrix address pieces
    const int arow = lane & 15, ahalf = lane >> 4;
    // B ldmatrix: seg = lane>>3
    const int seg = lane >> 3, lr = lane & 7;
    const int brow_off = (seg >> 1) * 8 + lr;
    const int bkh = seg & 1;

    auto stage = [&](int st, int buf) {
        const int kb = st * 32;
        uint32_t xh = smb + buf * GX_ST;
        uint32_t xl = xh + 10240;
        uint32_t wh = xl + 10240;
        uint32_t wl = wh + 5120;
#pragma unroll
        for (int p = 0; p < 4; p++) {
            int row = xrow + p * 32;
            uint32_t d = (uint32_t)(row * 80 + xch * 16);
            const __half* sx = &g_xh[(size_t)(m0 + row) * INF + kb + xch * 8];
            const __half* sl = &g_xl[(size_t)(m0 + row) * INF + kb + xch * 8];
            cp16(xh + d, sx);
            cp16(xl + d, sl);
        }
#pragma unroll
        for (int p = 0; p < 2; p++) {
            int row = xrow + p * 32;                 // 0..63
            uint32_t d = (uint32_t)(row * 80 + xch * 16);
            cp16(wh + d, &g_wh[(size_t)(n0 + row) * INF + kb + xch * 8]);
            cp16(wl + d, &g_wl[(size_t)(n0 + row) * INF + kb + xch * 8]);
        }
        asm volatile("cp.async.commit_group;" ::: "memory");
    };

    stage(0, 0);
#pragma unroll 1
    for (int st = 0; st < INF / 32; st++) {
        const int buf = st & 1;
        if (st + 1 < INF / 32) {
            stage(st + 1, buf ^ 1);
            asm volatile("cp.async.wait_group 1;" ::: "memory");
        } else {
            asm volatile("cp.async.wait_group 0;" ::: "memory");
        }
        __syncthreads();
        uint32_t xh = smb + buf * GX_ST;
        uint32_t xl = xh + 10240;
        uint32_t wh = xl + 10240;
        uint32_t wl = wh + 5120;
#pragma unroll
        for (int ks = 0; ks < 2; ks++) {
            unsigned axh[2][4], axl[2][4];
#pragma unroll
            for (int mf = 0; mf < 2; mf++) {
                uint32_t a = xh + (wm + mf * 16 + arow) * 80 + ks * 32 + ahalf * 16;
                ldm4(a, axh[mf][0], axh[mf][1], axh[mf][2], axh[mf][3]);
                uint32_t a2 = xl + (wm + mf * 16 + arow) * 80 + ks * 32 + ahalf * 16;
                ldm4(a2, axl[mf][0], axl[mf][1], axl[mf][2], axl[mf][3]);
            }
#pragma unroll
            for (int f = 0; f < 4; f++) {
                uint32_t ba = (uint32_t)((f * 16 + brow_off) * 80 + ks * 32 + bkh * 16);
                unsigned bh[4], bl[4];
                ldm4(wh + ba, bh[0], bh[1], bh[2], bh[3]);
                ldm4(wl + ba, bl[0], bl[1], bl[2], bl[3]);
#pragma unroll
                for (int g = 0; g < 2; g++) {
#pragma unroll
                    for (int mf = 0; mf < 2; mf++) {
                        float* C = acc[f * 2 + g][mf];
                        mma16816(C, axh[mf][0], axh[mf][1], axh[mf][2], axh[mf][3],
                                 bh[2 * g], bh[2 * g + 1]);
                        mma16816(C, axl[mf][0], axl[mf][1], axl[mf][2], axl[mf][3],
                                 bh[2 * g], bh[2 * g + 1]);
                        mma16816(C, axh[mf][0], axh[mf][1], axh[mf][2], axh[mf][3],
                                 bl[2 * g], bl[2 * g + 1]);
                    }
                }
            }
        }
        __syncthreads();
    }

    // epilogue: bias, write fp32 h + fp16 hb
#pragma unroll
    for (int f = 0; f < 8; f++) {
        int col = f * 8 + (lane & 3) * 2;
        float2 bv = *(const float2*)&b[n0 + col];
#pragma unroll
        for (int mf = 0; mf < 2; mf++) {
            float* C = acc[f][mf];
            int m = m0 + wm + mf * 16 + (lane >> 2);
            float c0 = C[0] + bv.x, c1 = C[1] + bv.y;
            float c2 = C[2] + bv.x, c3 = C[3] + bv.y;
            *(float2*)&g_h[(size_t)m * OUTF + n0 + col] = make_float2(c0, c1);
            *(float2*)&g_h[(size_t)(m + 8) * OUTF + n0 + col] = make_float2(c2, c3);
            *(unsigned*)&g_hb[(size_t)(hd * NN + m) * 64 + col] = pack_f16x2(c1, c0);
            *(unsigned*)&g_hb[(size_t)(hd * NN + m + 8) * 64 + col] = pack_f16x2(c3, c2);
        }
    }
}

// =====================================================================
// Kernel B1: a0/a1 per (head,node) + per-head a1max
// =====================================================================
__global__ __launch_bounds__(256) void param1_kernel(const float* __restrict__ aw) {
    const int tid = threadIdx.x;
    const int gw = blockIdx.x * 8 + (tid >> 5);
    const int lane = tid & 31;
    const int i = gw >> 3;
    const int hd = gw & 7;
    if (i >= NN) return;
    float h0 = g_h[i * OUTF + hd * 64 + lane];
    float h1 = g_h[i * OUTF + hd * 64 + lane + 32];
    float w00 = aw[hd * 128 + lane * 2 + 0];
    float w01 = aw[hd * 128 + lane * 2 + 1];
    float w10 = aw[hd * 128 + (lane + 32) * 2 + 0];
    float w11 = aw[hd * 128 + (lane + 32) * 2 + 1];
    float a0 = h0 * w00 + h1 * w10;
    float a1 = h0 * w01 + h1 * w11;
#pragma unroll
    for (int o = 16; o > 0; o >>= 1) {
        a0 += __shfl_xor_sync(0xffffffffu, a0, o);
        a1 += __shfl_xor_sync(0xffffffffu, a1, o);
    }
    if (lane == 0) {
        g_a0a1[hd * NN + i] = make_float2(a0, a1);
        atomicMax(&g_a1max[hd], fkey(a1));
    }
}

// =====================================================================
// Kernel B2: build scaled exp tables
// =====================================================================
__global__ __launch_bounds__(256) void param2_kernel() {
    int g = blockIdx.x * 256 + threadIdx.x;
    if (g >= H * NN) return;
    int hd = g / NN;
    float2 a = g_a0a1[g];
    float a1max = funkey(g_a1max[hd]);
    float z = a.x + a1max;
    float sl = (z > 0.f) ? z : 0.2f * z;
    float4 ai, aj;
    ai.x = ECAP * expf(a.x - sl);
    ai.y = ECAP * expf(0.2f * a.x - sl);
    ai.z = -a.x;
    ai.w = 0.f;
    aj.x = a.y;
    aj.y = expf(a.y);
    aj.z = expf(0.2f * a.y);
    aj.w = 0.f;
    g_ai[g] = ai;
    g_aj[g] = aj;
}

// =====================================================================
// Kernel C: adj -> bitmask
// =====================================================================
__global__ __launch_bounds__(256) void bits_kernel(const int* __restrict__ adj) {
    const int gw = blockIdx.x * 8 + (threadIdx.x >> 5);
    const int lane = threadIdx.x & 31;
    const int i = gw / NW;
    const int jw = gw % NW;
    if (i >= NN) return;
    int v = adj[i * NN + jw * 32 + lane];
    unsigned m = __ballot_sync(0xffffffffu, v > 0);
    if (lane == 0) g_bits[i * NW + jw] = m;
}

// =====================================================================
// Kernel D: fp16 HMMA attention, SINGLE product E*h.
// Grid (48, 8), 128 threads, M=32 rows/warp.
// =====================================================================
__global__ __launch_bounds__(128, 3) void attn_kernel(float* __restrict__ out) {
    __shared__ __align__(16) char   sB[2][8192];
    __shared__ __align__(16) float4 sAj[2][64];

    const int tid = threadIdx.x;
    const int wid = tid >> 5;
    const int lane = tid & 31;
    const int hd = blockIdx.y;
    const int i0 = blockIdx.x * 128;
    const int gr = lane >> 2;
    const int qc = (lane & 3) * 2;
    const int mb = wid * 32;

    const uint32_t smB = smem_u32(&sB[0][0]);
    const uint32_t smA = smem_u32(&sAj[0][0]);

    uint32_t sdst[4];
#pragma unroll
    for (int p = 0; p < 4; p++) {
        int idx = tid + p * 128;
        int sj = idx >> 3, sc = idx & 7;
        sdst[p] = (uint32_t)(sj * 128 + ((sc ^ (sj & 7)) << 4));
    }
    const char* srcH = (const char*)(g_hb + (size_t)hd * NN * 64);

    const int lg = lane >> 3, lr = lane & 7;
    const int joff = (lg & 1) * 8 + lr;
    const int nsel = lg >> 1;
    const uint32_t lmb = (uint32_t)(joff * 128);
    const int jm = joff & 7;

    float4 ai[4];
#pragma unroll
    for (int r = 0; r < 4; r++) ai[r] = g_ai[hd * NN + i0 + mb + gr + r * 8];
    const uint2* mrow[4];
#pragma unroll
    for (int r = 0; r < 4; r++)
        mrow[r] = (const uint2*)(g_bits + (size_t)(i0 + mb + gr + r * 8) * NW);

    float accA[8][4], accB[8][4];
#pragma unroll
    for (int n = 0; n < 8; n++)
#pragma unroll
        for (int c = 0; c < 4; c++) { accA[n][c] = 0.f; accB[n][c] = 0.f; }
    float lacc[4] = {0.f, 0.f, 0.f, 0.f};

    {
        uint32_t bh = smB;
#pragma unroll
        for (int p = 0; p < 4; p++)
            cp16(bh + sdst[p], srcH + (size_t)(tid + p * 128) * 16);
        if (tid < 64) cp16(smA + tid * 16, &g_aj[hd * NN + tid]);
        asm volatile("cp.async.commit_group;" ::: "memory");
    }

#pragma unroll 1
    for (int jt = 0; jt < NN / 64; jt++) {
        const int s = jt & 1;

        uint2 M[4];
#pragma unroll
        for (int r = 0; r < 4; r++) M[r] = mrow[r][jt];

        if (jt + 1 < NN / 64) {
            uint32_t bh = smB + (s ^ 1) * 8192;
#pragma unroll
            for (int p = 0; p < 4; p++) {
                size_t go = (size_t)(jt + 1) * 8192 + (size_t)(tid + p * 128) * 16;
                cp16(bh + sdst[p], srcH + go);
            }
            if (tid < 64) cp16(smA + (s ^ 1) * 1024 + tid * 16,
                               &g_aj[hd * NN + (jt + 1) * 64 + tid]);
            asm volatile("cp.async.commit_group;" ::: "memory");
            asm volatile("cp.async.wait_group 1;" ::: "memory");
        } else {
            asm volatile("cp.async.wait_group 0;" ::: "memory");
        }
        __syncthreads();

        const uint32_t bh = smB + s * 8192;
        const float4* ajb = &sAj[s][0];

        unsigned mk[4][4];
#pragma unroll
        for (int r = 0; r < 4; r++) {
            mk[r][0] = M[r].x & 0xffffu;
            mk[r][1] = M[r].x >> 16;
            mk[r][2] = M[r].y & 0xffffu;
            mk[r][3] = M[r].y >> 16;
        }

#pragma unroll
        for (int kk = 0; kk < 4; kk++) {
            float4 aj0 = ajb[kk * 16 + qc];
            float4 aj1 = ajb[kk * 16 + qc + 1];
            float4 aj8 = ajb[kk * 16 + qc + 8];
            float4 aj9 = ajb[kk * 16 + qc + 9];

            unsigned ah[4][2];
#pragma unroll
            for (int r = 0; r < 4; r++) {
                float4 a = ai[r];
                unsigned mm = mk[r][kk];
                float e0 = (aj0.x > a.z) ? (a.x * aj0.y) : (a.y * aj0.z);
                float e1 = (aj1.x > a.z) ? (a.x * aj1.y) : (a.y * aj1.z);
                float e8 = (aj8.x > a.z) ? (a.x * aj8.y) : (a.y * aj8.z);
                float e9 = (aj9.x > a.z) ? (a.x * aj9.y) : (a.y * aj9.z);
                e0 = ((mm >> qc) & 1u) ? e0 : 0.f;
                e1 = ((mm >> (qc + 1)) & 1u) ? e1 : 0.f;
                e8 = ((mm >> (qc + 8)) & 1u) ? e8 : 0.f;
                e9 = ((mm >> (qc + 9)) & 1u) ? e9 : 0.f;
                lacc[r] += (e0 + e1) + (e8 + e9);
                ah[r][0] = pack_f16x2(e1, e0);
                ah[r][1] = pack_f16x2(e9, e8);
            }

#pragma unroll
            for (int nh = 0; nh < 2; nh++) {
                const int nb0 = nh * 32, nb1 = nh * 32 + 16;
                uint32_t a0 = bh + kk * 2048 + lmb + ((((nb0 >> 3) + nsel) ^ jm) << 4);
                uint32_t a1 = bh + kk * 2048 + lmb + ((((nb1 >> 3) + nsel) ^ jm) << 4);
                unsigned t[8];
                ldm4t(a0, t[0], t[1], t[2], t[3]);
                ldm4t(a1, t[4], t[5], t[6], t[7]);
#pragma unroll
                for (int q = 0; q < 4; q++) {
                    mma16816(accA[nh * 4 + q], ah[0][0], ah[1][0], ah[0][1], ah[1][1],
                             t[2 * q], t[2 * q + 1]);
                    mma16816(accB[nh * 4 + q], ah[2][0], ah[3][0], ah[2][1], ah[3][1],
                             t[2 * q], t[2 * q + 1]);
                }
            }
        }
        __syncthreads();
    }

#pragma unroll
    for (int off = 1; off <= 2; off <<= 1)
#pragma unroll
        for (int r = 0; r < 4; r++)
            lacc[r] += __shfl_xor_sync(0xffffffffu, lacc[r], off);
    float inv[4];
#pragma unroll
    for (int r = 0; r < 4; r++) inv[r] = (lacc[r] > 0.f) ? (1.0f / lacc[r]) : 0.f;

#pragma unroll
    for (int f = 0; f < 2; f++) {
        float (*A)[4] = f ? accB : accA;
        float* b0 = out + (size_t)(i0 + mb + gr + f * 16) * OUTF + hd * 64 + qc;
        float* b1 = out + (size_t)(i0 + mb + gr + f * 16 + 8) * OUTF + hd * 64 + qc;
        float i0v = inv[f * 2], i1v = inv[f * 2 + 1];
#pragma unroll
        for (int nt = 0; nt < 8; nt++) {
            *(float2*)(b0 + nt * 8) = make_float2(A[nt][0] * i0v, A[nt][1] * i0v);
            *(float2*)(b1 + nt * 8) = make_float2(A[nt][2] * i1v, A[nt][3] * i1v);
        }
    }
}

// =====================================================================
extern "C" void kernel_launch(void* const* d_in, const int* in_sizes, int n_in,
                              void* d_out, int out_size) {
    const float* x = (const float*)d_in[0];
    const int* adj = (const int*)d_in[1];
    const float* W = (const float*)d_in[2];
    const float* b = (const float*)d_in[3];
    const float* aw = (const float*)d_in[4];
    float* out = (float*)d_out;

    cudaFuncSetAttribute(gemm_h_kernel, cudaFuncAttributeMaxDynamicSharedMemorySize,
                         GX_TOT);

    init_kernel<<<1, 32>>>();
    cvt_kernel<<<(NN * INF / 4 + OUTF * INF / 4 + 255) / 256, 256>>>(x, W);
    gemm_h_kernel<<<dim3(NN / 128, H), 128, GX_TOT>>>(b);
    param1_kernel<<<(NN * H) / 8, 256>>>(aw);
    param2_kernel<<<(H * NN + 255) / 256, 256>>>();
    bits_kernel<<<(NN * NW) / 8, 256>>>(adj);
    attn_kernel<<<dim3(NN / 128, H), 128>>>(out);
}

// round 8
// speedup vs baseline: 5.4295x; 1.1376x over previous
#include <cuda_runtime.h>
#include <cuda_fp16.h>
#include <cstdint>

#define NN   6144
#define INF  512
#define H    8
#define OUTF 512
#define NW   192
#define ECAP 28000.0f

// ---------------- scratch ----------------
__device__ __align__(16) float    g_h[NN * OUTF];
__device__ __align__(16) float2   g_a0a1[H * NN];
__device__ __align__(16) float2   g_ai2[H * NN];           // {u', u5'}
__device__ __align__(16) float4   g_ajp[H * NN / 2];       // per j-pair {v0,v1,v50,v51}
__device__ unsigned g_a1max[H];
__device__ __align__(16) unsigned g_bits[NN * NW];
__device__ __align__(16) __half   g_hb[H * NN * 64];       // [head][j][d] fp16
__device__ __align__(16) __half   g_xh[NN * INF];
__device__ __align__(16) __half   g_xl[NN * INF];
__device__ __align__(16) __half   g_wh[OUTF * INF];
__device__ __align__(16) __half   g_wl[OUTF * INF];

// ---------------- helpers ----------------
__device__ __forceinline__ unsigned pack_f16x2(float hi, float lo) {
    unsigned r;
    asm("cvt.rn.f16x2.f32 %0, %1, %2;" : "=r"(r) : "f"(hi), "f"(lo));
    return r;
}
__device__ __forceinline__ uint32_t smem_u32(const void* p) {
    uint32_t a;
    asm("{ .reg .u64 t; cvta.to.shared.u64 t, %1; cvt.u32.u64 %0, t; }" : "=r"(a) : "l"(p));
    return a;
}
__device__ __forceinline__ void cp16(uint32_t dst, const void* src) {
    asm volatile("cp.async.cg.shared.global [%0], [%1], 16;" :: "r"(dst), "l"(src));
}
__device__ __forceinline__ void ldm4(uint32_t addr, unsigned& r0, unsigned& r1,
                                     unsigned& r2, unsigned& r3) {
    asm volatile("ldmatrix.sync.aligned.m8n8.x4.shared.b16 {%0,%1,%2,%3}, [%4];"
                 : "=r"(r0), "=r"(r1), "=r"(r2), "=r"(r3) : "r"(addr));
}
__device__ __forceinline__ void ldm4t(uint32_t addr, unsigned& r0, unsigned& r1,
                                      unsigned& r2, unsigned& r3) {
    asm volatile("ldmatrix.sync.aligned.m8n8.x4.trans.shared.b16 {%0,%1,%2,%3}, [%4];"
                 : "=r"(r0), "=r"(r1), "=r"(r2), "=r"(r3) : "r"(addr));
}
__device__ __forceinline__ void mma16816(float* c, unsigned a0, unsigned a1,
                                         unsigned a2, unsigned a3,
                                         unsigned b0, unsigned b1) {
    asm volatile(
        "mma.sync.aligned.m16n8k16.row.col.f32.f16.f16.f32 "
        "{%0,%1,%2,%3},{%4,%5,%6,%7},{%8,%9},{%0,%1,%2,%3};"
        : "+f"(c[0]), "+f"(c[1]), "+f"(c[2]), "+f"(c[3])
        : "r"(a0), "r"(a1), "r"(a2), "r"(a3), "r"(b0), "r"(b1));
}
__device__ __forceinline__ unsigned long long packf2(float x) {
    unsigned long long r;
    asm("mov.b64 %0, {%1, %1};" : "=l"(r) : "f"(x));
    return r;
}
__device__ __forceinline__ void mul2(unsigned long long& d, unsigned long long a,
                                     unsigned long long b) {
    asm("mul.rn.f32x2 %0, %1, %2;" : "=l"(d) : "l"(a), "l"(b));
}
__device__ __forceinline__ void unp2(unsigned long long v, float& lo, float& hi) {
    asm("mov.b64 {%0, %1}, %2;" : "=f"(lo), "=f"(hi) : "l"(v));
}
__device__ __forceinline__ unsigned fkey(float f) {
    unsigned b = __float_as_uint(f);
    return (b & 0x80000000u) ? ~b : (b | 0x80000000u);
}
__device__ __forceinline__ float funkey(unsigned k) {
    unsigned b = (k & 0x80000000u) ? (k & 0x7fffffffu) : ~k;
    return __uint_as_float(b);
}

// =====================================================================
__global__ void init_kernel() {
    if (threadIdx.x < H) g_a1max[threadIdx.x] = 0u;
}

// =====================================================================
// Kernel CV: split x and W into fp16 hi/lo
// =====================================================================
__global__ __launch_bounds__(256) void cvt_kernel(const float* __restrict__ x,
                                                  const float* __restrict__ W) {
    int t = blockIdx.x * 256 + threadIdx.x;
    const int NX = NN * INF / 4;
    const int NWW = OUTF * INF / 4;
    if (t < NX) {
        float4 v = *(const float4*)&x[t * 4];
        unsigned h0 = pack_f16x2(v.y, v.x);
        unsigned h1 = pack_f16x2(v.w, v.z);
        float r0 = v.x - __half2float(__ushort_as_half((unsigned short)(h0 & 0xffff)));
        float r1 = v.y - __half2float(__ushort_as_half((unsigned short)(h0 >> 16)));
        float r2 = v.z - __half2float(__ushort_as_half((unsigned short)(h1 & 0xffff)));
        float r3 = v.w - __half2float(__ushort_as_half((unsigned short)(h1 >> 16)));
        *(uint2*)&g_xh[t * 4] = make_uint2(h0, h1);
        *(uint2*)&g_xl[t * 4] = make_uint2(pack_f16x2(r1, r0), pack_f16x2(r3, r2));
    } else if (t < NX + NWW) {
        int u = t - NX;
        float4 v = *(const float4*)&W[u * 4];
        unsigned h0 = pack_f16x2(v.y, v.x);
        unsigned h1 = pack_f16x2(v.w, v.z);
        float r0 = v.x - __half2float(__ushort_as_half((unsigned short)(h0 & 0xffff)));
        float r1 = v.y - __half2float(__ushort_as_half((unsigned short)(h0 >> 16)));
        float r2 = v.z - __half2float(__ushort_as_half((unsigned short)(h1 & 0xffff)));
        float r3 = v.w - __half2float(__ushort_as_half((unsigned short)(h1 >> 16)));
        *(uint2*)&g_wh[u * 4] = make_uint2(h0, h1);
        *(uint2*)&g_wl[u * 4] = make_uint2(pack_f16x2(r1, r0), pack_f16x2(r3, r2));
    }
}

// =====================================================================
// Kernel A: HMMA h = x@W^T + b, fused a0/a1 epilogue (param1 absorbed)
// =====================================================================
#define GX_ST 30720
#define GX_TOT (2 * GX_ST)

__global__ __launch_bounds__(128, 3) void gemm_h_kernel(
    const float* __restrict__ b, const float* __restrict__ aw) {
    extern __shared__ char gsm[];
    const uint32_t smb = smem_u32(gsm);
    const int tid = threadIdx.x;
    const int wid = tid >> 5;
    const int lane = tid & 31;
    const int m0 = blockIdx.x * 128;
    const int hd = blockIdx.y;
    const int n0 = hd * 64;
    const int wm = wid * 32;

    float acc[8][2][4];
#pragma unroll
    for (int f = 0; f < 8; f++)
#pragma unroll
        for (int m = 0; m < 2; m++)
#pragma unroll
            for (int c = 0; c < 4; c++) acc[f][m][c] = 0.f;

    const int xrow = tid >> 2, xch = tid & 3;
    const int arow = lane & 15, ahalf = lane >> 4;
    const int seg = lane >> 3, lr = lane & 7;
    const int brow_off = (seg >> 1) * 8 + lr;
    const int bkh = seg & 1;

    auto stage = [&](int st, int buf) {
        const int kb = st * 32;
        uint32_t xh = smb + buf * GX_ST;
        uint32_t xl = xh + 10240;
        uint32_t wh = xl + 10240;
        uint32_t wl = wh + 5120;
#pragma unroll
        for (int p = 0; p < 4; p++) {
            int row = xrow + p * 32;
            uint32_t d = (uint32_t)(row * 80 + xch * 16);
            cp16(xh + d, &g_xh[(size_t)(m0 + row) * INF + kb + xch * 8]);
            cp16(xl + d, &g_xl[(size_t)(m0 + row) * INF + kb + xch * 8]);
        }
#pragma unroll
        for (int p = 0; p < 2; p++) {
            int row = xrow + p * 32;
            uint32_t d = (uint32_t)(row * 80 + xch * 16);
            cp16(wh + d, &g_wh[(size_t)(n0 + row) * INF + kb + xch * 8]);
            cp16(wl + d, &g_wl[(size_t)(n0 + row) * INF + kb + xch * 8]);
        }
        asm volatile("cp.async.commit_group;" ::: "memory");
    };

    stage(0, 0);
#pragma unroll 1
    for (int st = 0; st < INF / 32; st++) {
        const int buf = st & 1;
        if (st + 1 < INF / 32) {
            stage(st + 1, buf ^ 1);
            asm volatile("cp.async.wait_group 1;" ::: "memory");
        } else {
            asm volatile("cp.async.wait_group 0;" ::: "memory");
        }
        __syncthreads();
        uint32_t xh = smb + buf * GX_ST;
        uint32_t xl = xh + 10240;
        uint32_t wh = xl + 10240;
        uint32_t wl = wh + 5120;
#pragma unroll
        for (int ks = 0; ks < 2; ks++) {
            unsigned axh[2][4], axl[2][4];
#pragma unroll
            for (int mf = 0; mf < 2; mf++) {
                ldm4(xh + (wm + mf * 16 + arow) * 80 + ks * 32 + ahalf * 16,
                     axh[mf][0], axh[mf][1], axh[mf][2], axh[mf][3]);
                ldm4(xl + (wm + mf * 16 + arow) * 80 + ks * 32 + ahalf * 16,
                     axl[mf][0], axl[mf][1], axl[mf][2], axl[mf][3]);
            }
#pragma unroll
            for (int f = 0; f < 4; f++) {
                uint32_t ba = (uint32_t)((f * 16 + brow_off) * 80 + ks * 32 + bkh * 16);
                unsigned bhf[4], blf[4];
                ldm4(wh + ba, bhf[0], bhf[1], bhf[2], bhf[3]);
                ldm4(wl + ba, blf[0], blf[1], blf[2], blf[3]);
#pragma unroll
                for (int g = 0; g < 2; g++) {
#pragma unroll
                    for (int mf = 0; mf < 2; mf++) {
                        float* C = acc[f * 2 + g][mf];
                        mma16816(C, axh[mf][0], axh[mf][1], axh[mf][2], axh[mf][3],
                                 bhf[2 * g], bhf[2 * g + 1]);
                        mma16816(C, axl[mf][0], axl[mf][1], axl[mf][2], axl[mf][3],
                                 bhf[2 * g], bhf[2 * g + 1]);
                        mma16816(C, axh[mf][0], axh[mf][1], axh[mf][2], axh[mf][3],
                                 blf[2 * g], blf[2 * g + 1]);
                    }
                }
            }
        }
        __syncthreads();
    }

    // epilogue: bias, write fp32 h + fp16 hb, fused a0/a1 dots
    const int qc2 = (lane & 3) * 2;
    float dot[4][2];
#pragma unroll
    for (int r = 0; r < 4; r++) { dot[r][0] = 0.f; dot[r][1] = 0.f; }

#pragma unroll
    for (int f = 0; f < 8; f++) {
        int col = f * 8 + qc2;
        float2 bv = *(const float2*)&b[n0 + col];
        float4 awv = *(const float4*)&aw[hd * 128 + col * 2];  // {a00,a01,a10,a11}
#pragma unroll
        for (int mf = 0; mf < 2; mf++) {
            float* C = acc[f][mf];
            int m = m0 + wm + mf * 16 + (lane >> 2);
            float c0 = C[0] + bv.x, c1 = C[1] + bv.y;
            float c2 = C[2] + bv.x, c3 = C[3] + bv.y;
            *(float2*)&g_h[(size_t)m * OUTF + n0 + col] = make_float2(c0, c1);
            *(float2*)&g_h[(size_t)(m + 8) * OUTF + n0 + col] = make_float2(c2, c3);
            *(unsigned*)&g_hb[(size_t)(hd * NN + m) * 64 + col] = pack_f16x2(c1, c0);
            *(unsigned*)&g_hb[(size_t)(hd * NN + m + 8) * 64 + col] = pack_f16x2(c3, c2);
            dot[mf * 2][0] += c0 * awv.x + c1 * awv.z;
            dot[mf * 2][1] += c0 * awv.y + c1 * awv.w;
            dot[mf * 2 + 1][0] += c2 * awv.x + c3 * awv.z;
            dot[mf * 2 + 1][1] += c2 * awv.y + c3 * awv.w;
        }
    }
    // reduce over 4 lanes of the row group
#pragma unroll
    for (int off = 1; off <= 2; off <<= 1)
#pragma unroll
        for (int r = 0; r < 4; r++) {
            dot[r][0] += __shfl_xor_sync(0xffffffffu, dot[r][0], off);
            dot[r][1] += __shfl_xor_sync(0xffffffffu, dot[r][1], off);
        }
    float a1loc = fmaxf(fmaxf(dot[0][1], dot[1][1]), fmaxf(dot[2][1], dot[3][1]));
    if ((lane & 3) == 0) {
        int mbase = m0 + wm + (lane >> 2);
        g_a0a1[hd * NN + mbase] = make_float2(dot[0][0], dot[0][1]);
        g_a0a1[hd * NN + mbase + 8] = make_float2(dot[1][0], dot[1][1]);
        g_a0a1[hd * NN + mbase + 16] = make_float2(dot[2][0], dot[2][1]);
        g_a0a1[hd * NN + mbase + 24] = make_float2(dot[3][0], dot[3][1]);
    }
#pragma unroll
    for (int off = 16; off > 0; off >>= 1)
        a1loc = fmaxf(a1loc, __shfl_xor_sync(0xffffffffu, a1loc, off));
    if (lane == 0) atomicMax(&g_a1max[hd], fkey(a1loc));
}

// =====================================================================
// Kernel B2: build scaled exp tables
// =====================================================================
__global__ __launch_bounds__(256) void param2_kernel() {
    int g = blockIdx.x * 256 + threadIdx.x;    // g = hd*NN + i
    if (g >= H * NN) return;
    int hd = g / NN;
    int i = g - hd * NN;
    float2 a = g_a0a1[g];
    float a1max = funkey(g_a1max[hd]);
    float z = a.x + a1max;
    float sl = (z > 0.f) ? z : 0.2f * z;
    g_ai2[g] = make_float2(ECAP * expf(a.x - sl), ECAP * expf(0.2f * a.x - sl));
    float v = expf(a.y);
    float v5 = expf(0.2f * a.y);
    float* dst = (float*)&g_ajp[hd * (NN / 2) + (i >> 1)];
    int o = i & 1;
    dst[o] = v;
    dst[2 + o] = v5;
}

// =====================================================================
// Kernel C: adj -> bitmask
// =====================================================================
__global__ __launch_bounds__(256) void bits_kernel(const int* __restrict__ adj) {
    const int gw = blockIdx.x * 8 + (threadIdx.x >> 5);
    const int lane = threadIdx.x & 31;
    const int i = gw / NW;
    const int jw = gw % NW;
    if (i >= NN) return;
    int v = adj[i * NN + jw * 32 + lane];
    unsigned m = __ballot_sync(0xffffffffu, v > 0);
    if (lane == 0) g_bits[i * NW + jw] = m;
}

// =====================================================================
// Kernel D: fp16 HMMA attention. E = max(u'·v, u5'·v5) via mul.f32x2.
// Row sums via all-ones B MMAs. Grid (48, 8), 128 threads.
// =====================================================================
#define ONESF16 0x3C003C00u

__global__ __launch_bounds__(128, 3) void attn_kernel(float* __restrict__ out) {
    __shared__ __align__(16) char   sB[2][8192];
    __shared__ __align__(16) float4 sAjp[2][32];

    const int tid = threadIdx.x;
    const int wid = tid >> 5;
    const int lane = tid & 31;
    const int hd = blockIdx.y;
    const int i0 = blockIdx.x * 128;
    const int gr = lane >> 2;
    const int l3 = lane & 3;
    const int qc = l3 * 2;
    const int mb = wid * 32;

    const uint32_t smB = smem_u32(&sB[0][0]);
    const uint32_t smA = smem_u32(&sAjp[0][0]);

    uint32_t sdst[4];
#pragma unroll
    for (int p = 0; p < 4; p++) {
        int idx = tid + p * 128;
        int sj = idx >> 3, sc = idx & 7;
        sdst[p] = (uint32_t)(sj * 128 + ((sc ^ (sj & 7)) << 4));
    }
    const char* srcH = (const char*)(g_hb + (size_t)hd * NN * 64);
    const float4* srcA = &g_ajp[hd * (NN / 2)];

    const int lg = lane >> 3, lr = lane & 7;
    const int joff = (lg & 1) * 8 + lr;
    const int nsel = lg >> 1;
    const uint32_t lmb = (uint32_t)(joff * 128);
    const int jm = joff & 7;

    // per-row packed u'/u5'
    unsigned long long uu[4], u5[4];
#pragma unroll
    for (int r = 0; r < 4; r++) {
        float2 a = g_ai2[hd * NN + i0 + mb + gr + r * 8];
        uu[r] = packf2(a.x);
        u5[r] = packf2(a.y);
    }
    const uint2* mrow[4];
#pragma unroll
    for (int r = 0; r < 4; r++)
        mrow[r] = (const uint2*)(g_bits + (size_t)(i0 + mb + gr + r * 8) * NW);

    float accA[8][4], accB[8][4], accSA[4], accSB[4];
#pragma unroll
    for (int n = 0; n < 8; n++)
#pragma unroll
        for (int c = 0; c < 4; c++) { accA[n][c] = 0.f; accB[n][c] = 0.f; }
#pragma unroll
    for (int c = 0; c < 4; c++) { accSA[c] = 0.f; accSB[c] = 0.f; }

    {
#pragma unroll
        for (int p = 0; p < 4; p++)
            cp16(smB + sdst[p], srcH + (size_t)(tid + p * 128) * 16);
        if (tid < 32) cp16(smA + tid * 16, srcA + tid);
        asm volatile("cp.async.commit_group;" ::: "memory");
    }

#pragma unroll 1
    for (int jt = 0; jt < NN / 64; jt++) {
        const int s = jt & 1;

        uint2 M[4];
#pragma unroll
        for (int r = 0; r < 4; r++) M[r] = mrow[r][jt];

        if (jt + 1 < NN / 64) {
            uint32_t bh = smB + (s ^ 1) * 8192;
#pragma unroll
            for (int p = 0; p < 4; p++)
                cp16(bh + sdst[p],
                     srcH + (size_t)(jt + 1) * 8192 + (size_t)(tid + p * 128) * 16);
            if (tid < 32) cp16(smA + (s ^ 1) * 512 + tid * 16,
                               srcA + (jt + 1) * 32 + tid);
            asm volatile("cp.async.commit_group;" ::: "memory");
            asm volatile("cp.async.wait_group 1;" ::: "memory");
        } else {
            asm volatile("cp.async.wait_group 0;" ::: "memory");
        }
        __syncthreads();

        const uint32_t bh = smB + s * 8192;
        const float4* ajb = &sAjp[s][0];

        unsigned mk[4][4];
#pragma unroll
        for (int r = 0; r < 4; r++) {
            mk[r][0] = M[r].x & 0xffffu;
            mk[r][1] = M[r].x >> 16;
            mk[r][2] = M[r].y & 0xffffu;
            mk[r][3] = M[r].y >> 16;
        }

#pragma unroll
        for (int kk = 0; kk < 4; kk++) {
            ulonglong2 va = *(const ulonglong2*)&ajb[kk * 8 + l3];      // {v01, v501}
            ulonglong2 vb = *(const ulonglong2*)&ajb[kk * 8 + 4 + l3];  // j+8 pair

            unsigned ah[4][2];
#pragma unroll
            for (int r = 0; r < 4; r++) {
                unsigned mm = mk[r][kk];
                unsigned long long p01, q01, p89, q89;
                mul2(p01, uu[r], va.x);
                mul2(q01, u5[r], va.y);
                mul2(p89, uu[r], vb.x);
                mul2(q89, u5[r], vb.y);
                float p0, p1, q0, q1, p8, p9, q8, q9;
                unp2(p01, p0, p1);
                unp2(q01, q0, q1);
                unp2(p89, p8, p9);
                unp2(q89, q8, q9);
                float e0 = fmaxf(p0, q0), e1 = fmaxf(p1, q1);
                float e8 = fmaxf(p8, q8), e9 = fmaxf(p9, q9);
                e0 = ((mm >> qc) & 1u) ? e0 : 0.f;
                e1 = ((mm >> (qc + 1)) & 1u) ? e1 : 0.f;
                e8 = ((mm >> (qc + 8)) & 1u) ? e8 : 0.f;
                e9 = ((mm >> (qc + 9)) & 1u) ? e9 : 0.f;
                ah[r][0] = pack_f16x2(e1, e0);
                ah[r][1] = pack_f16x2(e9, e8);
            }

            // row-sum MMAs (ones B, no ldmatrix)
            mma16816(accSA, ah[0][0], ah[1][0], ah[0][1], ah[1][1], ONESF16, ONESF16);
            mma16816(accSB, ah[2][0], ah[3][0], ah[2][1], ah[3][1], ONESF16, ONESF16);

#pragma unroll
            for (int nh = 0; nh < 2; nh++) {
                const int nb0 = nh * 32, nb1 = nh * 32 + 16;
                uint32_t a0 = bh + kk * 2048 + lmb + ((((nb0 >> 3) + nsel) ^ jm) << 4);
                uint32_t a1 = bh + kk * 2048 + lmb + ((((nb1 >> 3) + nsel) ^ jm) << 4);
                unsigned t[8];
                ldm4t(a0, t[0], t[1], t[2], t[3]);
                ldm4t(a1, t[4], t[5], t[6], t[7]);
#pragma unroll
                for (int q = 0; q < 4; q++) {
                    mma16816(accA[nh * 4 + q], ah[0][0], ah[1][0], ah[0][1], ah[1][1],
                             t[2 * q], t[2 * q + 1]);
                    mma16816(accB[nh * 4 + q], ah[2][0], ah[3][0], ah[2][1], ah[3][1],
                             t[2 * q], t[2 * q + 1]);
                }
            }
        }
        __syncthreads();
    }

    // inverses straight from the ones-MMA accumulators (no shuffles needed)
    float inv[4];
    inv[0] = (accSA[0] > 0.f) ? (1.0f / accSA[0]) : 0.f;
    inv[1] = (accSA[2] > 0.f) ? (1.0f / accSA[2]) : 0.f;
    inv[2] = (accSB[0] > 0.f) ? (1.0f / accSB[0]) : 0.f;
    inv[3] = (accSB[2] > 0.f) ? (1.0f / accSB[2]) : 0.f;

#pragma unroll
    for (int f = 0; f < 2; f++) {
        float (*A)[4] = f ? accB : accA;
        float* b0 = out + (size_t)(i0 + mb + gr + f * 16) * OUTF + hd * 64 + qc;
        float* b1 = out + (size_t)(i0 + mb + gr + f * 16 + 8) * OUTF + hd * 64 + qc;
        float i0v = inv[f * 2], i1v = inv[f * 2 + 1];
#pragma unroll
        for (int nt = 0; nt < 8; nt++) {
            *(float2*)(b0 + nt * 8) = make_float2(A[nt][0] * i0v, A[nt][1] * i0v);
            *(float2*)(b1 + nt * 8) = make_float2(A[nt][2] * i1v, A[nt][3] * i1v);
        }
    }
}

// =====================================================================
extern "C" void kernel_launch(void* const* d_in, const int* in_sizes, int n_in,
                              void* d_out, int out_size) {
    const float* x = (const float*)d_in[0];
    const int* adj = (const int*)d_in[1];
    const float* W = (const float*)d_in[2];
    const float* b = (const float*)d_in[3];
    const float* aw = (const float*)d_in[4];
    float* out = (float*)d_out;

    cudaFuncSetAttribute(gemm_h_kernel, cudaFuncAttributeMaxDynamicSharedMemorySize,
                         GX_TOT);

    init_kernel<<<1, 32>>>();
    cvt_kernel<<<(NN * INF / 4 + OUTF * INF / 4 + 255) / 256, 256>>>(x, W);
    gemm_h_kernel<<<dim3(NN / 128, H), 128, GX_TOT>>>(b, aw);
    param2_kernel<<<(H * NN + 255) / 256, 256>>>();
    bits_kernel<<<(NN * NW) / 8, 256>>>(adj);
    attn_kernel<<<dim3(NN / 128, H), 128>>>(out);
}